// round 13
// baseline (speedup 1.0000x reference)
#include <cuda_runtime.h>
#include <cuda_fp16.h>
#include <cstdint>

// out[64,8192] = x[64,8192] @ blockdiag(blocks), 32 diagonal 256x256 blocks.
// Grid 128 = 32 blocks x 4 col-chunks of 64. Per CTA:
//   out[0:64, col0:col0+64] = x[0:64, k0:k0+256] @ B[k0:k0+256, col0:col0+64]
//
// Single-term fp16 HMMA (rel_err ~3e-4). R13: ZERO CTA barriers.
// 16 fully autonomous warps; warp (wm,wn) owns out tile 16x16 and full K=256,
// staging its own A(16x64) and B(64x16) chunks into a private 8KB smem region
// (double-buffered), __syncwarp only. A/B re-reads across warps hit L1/L2.

#define NROW 8192
#define SMEM_BYTES 131072        // 16 warps x 8KB

__device__ __forceinline__ uint32_t smem_u32(const void* p) {
    uint32_t a;
    asm("{ .reg .u64 t; cvta.to.shared.u64 t, %1; cvt.u32.u64 %0, t; }" : "=r"(a) : "l"(p));
    return a;
}
__device__ __forceinline__ void ldsm_x4(uint32_t* r, uint32_t addr) {
    asm volatile("ldmatrix.sync.aligned.m8n8.x4.shared.b16 {%0,%1,%2,%3}, [%4];"
                 : "=r"(r[0]), "=r"(r[1]), "=r"(r[2]), "=r"(r[3]) : "r"(addr));
}
__device__ __forceinline__ void ldsm_x4_t(uint32_t* r, uint32_t addr) {
    asm volatile("ldmatrix.sync.aligned.m8n8.x4.trans.shared.b16 {%0,%1,%2,%3}, [%4];"
                 : "=r"(r[0]), "=r"(r[1]), "=r"(r[2]), "=r"(r[3]) : "r"(addr));
}
__device__ __forceinline__ void mma_f16(float* d, const uint32_t* a, uint32_t b0, uint32_t b1) {
    asm volatile(
        "mma.sync.aligned.m16n8k16.row.col.f32.f16.f16.f32 "
        "{%0,%1,%2,%3}, {%4,%5,%6,%7}, {%8,%9}, {%0,%1,%2,%3};"
        : "+f"(d[0]), "+f"(d[1]), "+f"(d[2]), "+f"(d[3])
        : "r"(a[0]), "r"(a[1]), "r"(a[2]), "r"(a[3]), "r"(b0), "r"(b1));
}
__device__ __forceinline__ uint32_t h2u(__half2 h) { return *(uint32_t*)&h; }

__global__ void __launch_bounds__(512, 1)
block_diag_hmma(const float* __restrict__ x,
                const float* __restrict__ blocks,
                float* __restrict__ out) {
    extern __shared__ char smem[];
    const uint32_t sbase = smem_u32(smem);

    const int tid   = threadIdx.x;
    const int wid   = tid >> 5;
    const int lid   = tid & 31;
    const int bx    = blockIdx.x;
    const int dblk  = bx >> 2;
    const int chunk = bx & 3;
    const int k0    = dblk * 256;
    const int col0  = k0 + chunk * 64;

    const int wm = wid & 3;
    const int wn = wid >> 2;              // 0..3
    const int m_base = wm * 16;
    const int n_base = wn * 16;

    char* Wa = smem + wid * 8192;         // A bufs: +0, +2048
    char* Wb = Wa + 4096;                 // B bufs: +0, +2048
    const uint32_t sWa = sbase + (uint32_t)(wid * 8192);
    const uint32_t sWb = sWa + 4096;

    // ---- per-warp LDG of one chunk (A: 16x64 fp32, B: 64x16 fp32) ----
    auto ldgChunk = [&](int c, float4* va, float4* vb) {
        const int kg = k0 + c * 64;
        #pragma unroll
        for (int it = 0; it < 8; ++it) {
            int idx = it * 32 + lid;
            int kr = idx >> 2, sq = idx & 3;   // B: 64 rows x 4 f4
            vb[it] = *(const float4*)(blocks + (size_t)(kg + kr) * NROW
                                      + col0 + n_base + sq * 4);
        }
        #pragma unroll
        for (int it = 0; it < 8; ++it) {
            int idx = it * 32 + lid;
            int r = idx >> 4, sq = idx & 15;   // A: 16 rows x 16 f4
            va[it] = *(const float4*)(x + (size_t)(m_base + r) * NROW + kg + sq * 4);
        }
    };

    // ---- per-warp convert + STS into buffer `buf` ----
    auto stsChunk = [&](int buf, const float4* va, const float4* vb) {
        char* A = Wa + buf * 2048;
        char* B = Wb + buf * 2048;
        #pragma unroll
        for (int it = 0; it < 8; ++it) {
            int idx = it * 32 + lid;
            int kr = idx >> 2, sq = idx & 3;
            uint32_t off = (uint32_t)(kr * 32
                         + (((sq >> 1) ^ ((kr >> 2) & 1)) * 16) + (sq & 1) * 8);
            __half2 b01 = __floats2half2_rn(vb[it].x, vb[it].y);
            __half2 b23 = __floats2half2_rn(vb[it].z, vb[it].w);
            *(uint2*)(B + off) = make_uint2(h2u(b01), h2u(b23));
        }
        #pragma unroll
        for (int it = 0; it < 8; ++it) {
            int idx = it * 32 + lid;
            int r = idx >> 4, sq = idx & 15;
            uint32_t off = (uint32_t)(r * 128
                         + (((sq >> 1) ^ (r & 7)) * 16) + (sq & 1) * 8);
            __half2 a01 = __floats2half2_rn(va[it].x, va[it].y);
            __half2 a23 = __floats2half2_rn(va[it].z, va[it].w);
            *(uint2*)(A + off) = make_uint2(h2u(a01), h2u(a23));
        }
    };

    // ---- lane constants for ldsm ----
    const int l15  = lid & 15;
    const int lch  = lid >> 4;                       // 0/1
    const uint32_t a_lane = (uint32_t)(l15 * 128);   // + granule swizzle per ks
    const int a_rx = l15 & 7;
    const int b_g  = lch ^ ((lid >> 2) & 1);         // constant per lane (see note)
    const uint32_t b_lane = (uint32_t)(l15 * 32 + b_g * 16);

    float acc[2][4] = {};

    auto computeChunk = [&](int buf) {
        const uint32_t aB = sWa + (uint32_t)(buf * 2048);
        const uint32_t bB = sWb + (uint32_t)(buf * 2048);
        uint32_t a[4], b[4];
        #pragma unroll
        for (int ks = 0; ks < 4; ++ks) {
            uint32_t a_off = aB + a_lane + (uint32_t)((((ks * 2 + lch) ^ a_rx)) * 16);
            uint32_t b_off = bB + b_lane + (uint32_t)(ks * 512);
            ldsm_x4(a, a_off);
            ldsm_x4_t(b, b_off);
            mma_f16(acc[0], a, b[0], b[1]);
            mma_f16(acc[1], a, b[2], b[3]);
        }
    };

    // ---- warp-private pipeline, no CTA barriers ----
    float4 va[8], vb[8];
    ldgChunk(0, va, vb);
    stsChunk(0, va, vb);
    __syncwarp();

    #pragma unroll
    for (int c = 0; c < 4; ++c) {
        if (c < 3) ldgChunk(c + 1, va, vb);   // regs free: compute reads smem
        computeChunk(c & 1);
        if (c < 3) {
            stsChunk((c + 1) & 1, va, vb);
            __syncwarp();
        }
    }

    // ---- epilogue: warp's 16x16 tile ----
    const int grp = lid >> 2;
    const int tc  = lid & 3;
    const int row0 = m_base + grp;
    const int row1 = row0 + 8;
    #pragma unroll
    for (int nh = 0; nh < 2; ++nh) {
        int col = col0 + n_base + nh * 8 + tc * 2;
        *(float2*)(out + (size_t)row0 * NROW + col) = make_float2(acc[nh][0], acc[nh][1]);
        *(float2*)(out + (size_t)row1 * NROW + col) = make_float2(acc[nh][2], acc[nh][3]);
    }
}

extern "C" void kernel_launch(void* const* d_in, const int* in_sizes, int n_in,
                              void* d_out, int out_size) {
    const float* x      = (const float*)d_in[0];
    const float* blocks = (const float*)d_in[1];
    float* out = (float*)d_out;

    cudaFuncSetAttribute(block_diag_hmma,
                         cudaFuncAttributeMaxDynamicSharedMemorySize, SMEM_BYTES);
    block_diag_hmma<<<128, 512, SMEM_BYTES>>>(x, blocks, out);
}

// round 14
// speedup vs baseline: 1.1944x; 1.1944x over previous
#include <cuda_runtime.h>
#include <cuda_fp16.h>
#include <cstdint>

// out[64,8192] = x[64,8192] @ blockdiag(blocks), 32 diagonal 256x256 blocks.
// R14: grid 256 = 32 blocks x 8 col-chunks of 32; 512 threads, occupancy 2
// (296 slots -> single wave, ~2 independent CTAs/SM for cross-CTA overlap).
// Per CTA: out[0:64, col0:col0+32] = x[0:64, k0:k0+256] @ B[k0:k0+256, col0:col0+32]
// Single-term fp16 HMMA (rel_err ~2.9e-4). B staged fp32 via cp.async (0 regs),
// A LDG->cvt->STS in 2 low-register passes. Two barriers total.

#define NROW 8192

#define OFF_AH 0          // 32KB: A fp16, 64 rows x 512B, swizzled
#define OFF_BH 32768      // 16KB: B fp16, 256 rows x 64B, swizzled
#define OFF_BF 49152      // 32KB: B fp32 staging, 256 rows x 128B
#define SMEM_BYTES 81920

__device__ __forceinline__ uint32_t smem_u32(const void* p) {
    uint32_t a;
    asm("{ .reg .u64 t; cvta.to.shared.u64 t, %1; cvt.u32.u64 %0, t; }" : "=r"(a) : "l"(p));
    return a;
}
__device__ __forceinline__ void cp_async16(uint32_t s, const void* g) {
    asm volatile("cp.async.cg.shared.global [%0], [%1], 16;" :: "r"(s), "l"(g));
}
__device__ __forceinline__ void ldsm_x4(uint32_t* r, uint32_t addr) {
    asm volatile("ldmatrix.sync.aligned.m8n8.x4.shared.b16 {%0,%1,%2,%3}, [%4];"
                 : "=r"(r[0]), "=r"(r[1]), "=r"(r[2]), "=r"(r[3]) : "r"(addr));
}
__device__ __forceinline__ void ldsm_x2_t(uint32_t& r0, uint32_t& r1, uint32_t addr) {
    asm volatile("ldmatrix.sync.aligned.m8n8.x2.trans.shared.b16 {%0,%1}, [%2];"
                 : "=r"(r0), "=r"(r1) : "r"(addr));
}
__device__ __forceinline__ void mma_f16(float* d, const uint32_t* a, uint32_t b0, uint32_t b1) {
    asm volatile(
        "mma.sync.aligned.m16n8k16.row.col.f32.f16.f16.f32 "
        "{%0,%1,%2,%3}, {%4,%5,%6,%7}, {%8,%9}, {%0,%1,%2,%3};"
        : "+f"(d[0]), "+f"(d[1]), "+f"(d[2]), "+f"(d[3])
        : "r"(a[0]), "r"(a[1]), "r"(a[2]), "r"(a[3]), "r"(b0), "r"(b1));
}
__device__ __forceinline__ uint32_t h2u(__half2 h) { return *(uint32_t*)&h; }

__global__ void __launch_bounds__(512, 2)
block_diag_hmma(const float* __restrict__ x,
                const float* __restrict__ blocks,
                float* __restrict__ out) {
    extern __shared__ char smem[];
    const uint32_t sbase = smem_u32(smem);

    const int tid   = threadIdx.x;
    const int wid   = tid >> 5;
    const int lid   = tid & 31;
    const int bx    = blockIdx.x;
    const int dblk  = bx >> 3;
    const int chunk = bx & 7;
    const int k0    = dblk * 256;
    const int col0  = k0 + chunk * 32;

    // ---- 1) cp.async B fp32: 256 rows x 32 floats (128B rows) ----
    {
        const uint32_t bf = sbase + OFF_BF;
        #pragma unroll
        for (int p = 0; p < 4; ++p) {
            int idx = p * 512 + tid;
            int k  = idx >> 3;            // 0..255
            int n4 = idx & 7;             // f4 along 32 cols
            cp_async16(bf + (uint32_t)(k * 128 + n4 * 16),
                       blocks + (size_t)(k0 + k) * NROW + col0 + n4 * 4);
        }
        asm volatile("cp.async.commit_group;" ::: "memory");
    }

    // ---- 2) A: x[64][256] fp32 -> Ah fp16 swizzled; 2 passes, low regs ----
    {
        char* Ah = smem + OFF_AH;
        #pragma unroll
        for (int pp = 0; pp < 2; ++pp) {
            float4 va[4];
            #pragma unroll
            for (int p = 0; p < 4; ++p) {
                int ia = (pp * 4 + p) * 512 + tid;
                int m  = ia >> 6;
                int q  = ia & 63;
                va[p] = *(const float4*)(x + (size_t)m * NROW + k0 + q * 4);
            }
            #pragma unroll
            for (int p = 0; p < 4; ++p) {
                int ia = (pp * 4 + p) * 512 + tid;
                int m  = ia >> 6;
                int q  = ia & 63;
                int g = q >> 1, hh = q & 1;
                uint32_t offA = (uint32_t)(m * 512 + ((g ^ (m & 7)) * 16 + hh * 8));
                __half2 a01 = __floats2half2_rn(va[p].x, va[p].y);
                __half2 a23 = __floats2half2_rn(va[p].z, va[p].w);
                *(uint32_t*)(Ah + offA)     = h2u(a01);
                *(uint32_t*)(Ah + offA + 4) = h2u(a23);
            }
        }
    }

    asm volatile("cp.async.wait_group 0;" ::: "memory");
    __syncthreads();

    // ---- 3) convert B fp32 smem -> Bh fp16 swizzled (64B rows) ----
    {
        const char* BF = smem + OFF_BF;
        char* Bh = smem + OFF_BH;
        #pragma unroll
        for (int p = 0; p < 4; ++p) {
            int idx = p * 512 + tid;
            int k  = idx >> 3;
            int n4 = idx & 7;
            float4 v = *(const float4*)(BF + k * 128 + n4 * 16);
            // row k: 4 granules of 16B; swizzle g' = ng ^ ((k>>1)&3), +(k&1)*64 natural
            int ng = n4 >> 1;
            uint32_t off = (uint32_t)(k * 64 + ((ng ^ ((k >> 1) & 3)) * 16) + (n4 & 1) * 8);
            __half2 b01 = __floats2half2_rn(v.x, v.y);
            __half2 b23 = __floats2half2_rn(v.z, v.w);
            *(uint32_t*)(Bh + off)     = h2u(b01);
            *(uint32_t*)(Bh + off + 4) = h2u(b23);
        }
    }

    __syncthreads();

    // ---- 4) compute: 16 warps = 4m x 4n; warp tile 16x8; 16 ksteps ----
    const int wm = wid & 3;
    const int wn = wid >> 2;              // 0..3 -> cols wn*8..wn*8+7
    const int m_base = wm * 16;
    const int n_base = wn * 8;

    const int a_row = m_base + (lid & 15);
    const int a_ch  = lid >> 4;
    const int a_rx  = a_row & 7;
    const uint32_t a_rowbase = sbase + OFF_AH + (uint32_t)(a_row * 512);

    const int l15 = lid & 15;
    const uint32_t b_lane = sbase + OFF_BH
        + (uint32_t)(l15 * 64 + ((wn ^ ((l15 >> 1) & 3)) * 16));

    float acc[4] = {};
    uint32_t a[4];
    uint32_t b0, b1;

    #pragma unroll
    for (int ks = 0; ks < 16; ++ks) {
        uint32_t a_off = a_rowbase + (uint32_t)((((ks * 2 + a_ch) ^ a_rx)) * 16);
        ldsm_x4(a, a_off);
        ldsm_x2_t(b0, b1, b_lane + (uint32_t)(ks * 1024));   // 16 rows x 64B
        mma_f16(acc, a, b0, b1);
    }

    // ---- epilogue: 16x8 warp tile ----
    const int grp = lid >> 2;
    const int tc  = lid & 3;
    const int row0 = m_base + grp;
    const int row1 = row0 + 8;
    const int col  = col0 + n_base + tc * 2;
    *(float2*)(out + (size_t)row0 * NROW + col) = make_float2(acc[0], acc[1]);
    *(float2*)(out + (size_t)row1 * NROW + col) = make_float2(acc[2], acc[3]);
}

extern "C" void kernel_launch(void* const* d_in, const int* in_sizes, int n_in,
                              void* d_out, int out_size) {
    const float* x      = (const float*)d_in[0];
    const float* blocks = (const float*)d_in[1];
    float* out = (float*)d_out;

    cudaFuncSetAttribute(block_diag_hmma,
                         cudaFuncAttributeMaxDynamicSharedMemorySize, SMEM_BYTES);
    block_diag_hmma<<<256, 512, SMEM_BYTES>>>(x, blocks, out);
}

// round 15
// speedup vs baseline: 1.2694x; 1.0627x over previous
#include <cuda_runtime.h>
#include <cuda_fp16.h>
#include <cstdint>

// out[64,8192] = x[64,8192] @ blockdiag(blocks), 32 diagonal 256x256 blocks.
// Grid 128 = 32 blocks x 4 col-chunks of 64. Per CTA:
//   out[0:64, col0:col0+64] = x[0:64, k0:k0+256] @ B[k0:k0+256, col0:col0+64]
//
// Single-term fp16 HMMA (rel_err ~2.9e-4).
// R15: minimize L1 wavefronts. 16 warps = 2 K-halves x (4m x 2n) tiles of
// 16x32 (A x4 fragment reused across two B x4.trans -> 4 MMAs per kstep).
// LDSM wf/CTA: 3072 -> 1536. K-halves combined via 16KB smem reduce.

#define NROW 8192

#define OFF_AH  0          // 32KB: A fp16, 64 rows x 512B, swizzled
#define OFF_BH  32768      // 32KB: B fp16, 256 rows x 128B, swizzled
#define OFF_RED 65536      // 16KB: fp32 partials from K-half 1
#define SMEM_BYTES 81920

__device__ __forceinline__ uint32_t smem_u32(const void* p) {
    uint32_t a;
    asm("{ .reg .u64 t; cvta.to.shared.u64 t, %1; cvt.u32.u64 %0, t; }" : "=r"(a) : "l"(p));
    return a;
}
__device__ __forceinline__ void ldsm_x4(uint32_t* r, uint32_t addr) {
    asm volatile("ldmatrix.sync.aligned.m8n8.x4.shared.b16 {%0,%1,%2,%3}, [%4];"
                 : "=r"(r[0]), "=r"(r[1]), "=r"(r[2]), "=r"(r[3]) : "r"(addr));
}
__device__ __forceinline__ void ldsm_x4_t(uint32_t* r, uint32_t addr) {
    asm volatile("ldmatrix.sync.aligned.m8n8.x4.trans.shared.b16 {%0,%1,%2,%3}, [%4];"
                 : "=r"(r[0]), "=r"(r[1]), "=r"(r[2]), "=r"(r[3]) : "r"(addr));
}
__device__ __forceinline__ void mma_f16(float* d, const uint32_t* a, uint32_t b0, uint32_t b1) {
    asm volatile(
        "mma.sync.aligned.m16n8k16.row.col.f32.f16.f16.f32 "
        "{%0,%1,%2,%3}, {%4,%5,%6,%7}, {%8,%9}, {%0,%1,%2,%3};"
        : "+f"(d[0]), "+f"(d[1]), "+f"(d[2]), "+f"(d[3])
        : "r"(a[0]), "r"(a[1]), "r"(a[2]), "r"(a[3]), "r"(b0), "r"(b1));
}
__device__ __forceinline__ uint32_t h2u(__half2 h) { return *(uint32_t*)&h; }

__global__ void __launch_bounds__(512, 1)
block_diag_hmma(const float* __restrict__ x,
                const float* __restrict__ blocks,
                float* __restrict__ out) {
    extern __shared__ char smem[];
    const uint32_t sbase = smem_u32(smem);

    const int tid   = threadIdx.x;
    const int wid   = tid >> 5;
    const int lid   = tid & 31;
    const int bx    = blockIdx.x;
    const int dblk  = bx >> 2;
    const int chunk = bx & 3;
    const int k0    = dblk * 256;
    const int col0  = k0 + chunk * 64;

    // ================= stage phase =================
    // B first (unique bytes), then A; 8 f4 each per thread, cvt+STS inline.
    {
        char* Bh = smem + OFF_BH;
        #pragma unroll
        for (int p = 0; p < 8; ++p) {
            int idx = p * 512 + tid;
            int k  = idx >> 4;            // 0..255
            int n4 = idx & 15;            // f4 along 64 cols
            float4 v = *(const float4*)(blocks + (size_t)(k0 + k) * NROW + col0 + n4 * 4);
            int g = n4 >> 1;
            uint32_t off = (uint32_t)(k * 128 + ((g ^ (k & 7)) * 16) + (n4 & 1) * 8);
            __half2 b01 = __floats2half2_rn(v.x, v.y);
            __half2 b23 = __floats2half2_rn(v.z, v.w);
            *(uint32_t*)(Bh + off)     = h2u(b01);
            *(uint32_t*)(Bh + off + 4) = h2u(b23);
        }
        char* Ah = smem + OFF_AH;
        #pragma unroll
        for (int p = 0; p < 8; ++p) {
            int idx = p * 512 + tid;
            int m = idx >> 6;             // 0..63
            int q = idx & 63;             // f4 along K
            float4 v = *(const float4*)(x + (size_t)m * NROW + k0 + q * 4);
            int g = q >> 1;
            uint32_t off = (uint32_t)(m * 512 + ((g ^ (m & 7)) * 16) + (q & 1) * 8);
            __half2 a01 = __floats2half2_rn(v.x, v.y);
            __half2 a23 = __floats2half2_rn(v.z, v.w);
            *(uint32_t*)(Ah + off)     = h2u(a01);
            *(uint32_t*)(Ah + off + 4) = h2u(a23);
        }
    }

    __syncthreads();

    // ================= compute phase =================
    // 16 warps = 2 K-halves (h) x 4m x 2n; warp tile 16x32; 8 ksteps per half.
    const int h   = wid >> 3;             // K-half
    const int wl  = wid & 7;
    const int wm  = wl & 3;
    const int wn2 = wl >> 2;              // 0/1 -> n_base 0/32
    const int m_base = wm * 16;
    const int n_base = wn2 * 32;

    const int a_row = m_base + (lid & 15);
    const int a_ch  = lid >> 4;
    const int a_rx  = a_row & 7;
    const uint32_t a_rowbase = sbase + OFF_AH + (uint32_t)(a_row * 512);

    const int l15 = lid & 15;
    const int l7  = lid & 7;
    // two B n-tiles: t0 = wn2*2, t1 = wn2*2+1
    const uint32_t b_lane0 = sbase + OFF_BH
        + (uint32_t)(l15 * 128 + (((wn2 * 4 + 0 + (lid >> 4)) ^ l7) * 16));
    const uint32_t b_lane1 = sbase + OFF_BH
        + (uint32_t)(l15 * 128 + (((wn2 * 4 + 2 + (lid >> 4)) ^ l7) * 16));

    float acc[4][4] = {};                  // 4 n-subtiles of 8 cols
    uint32_t a[4], b0[4], b1[4];

    #pragma unroll
    for (int ks = 0; ks < 8; ++ks) {
        int G = (h * 8 + ks) * 2 + a_ch;   // global 16B granule along K
        uint32_t a_off = a_rowbase + (uint32_t)((G ^ a_rx) * 16);
        uint32_t brow  = (uint32_t)((h * 8 + ks) * 2048);   // 16 k-rows x 128B
        ldsm_x4(a, a_off);
        ldsm_x4_t(b0, b_lane0 + brow);
        ldsm_x4_t(b1, b_lane1 + brow);
        mma_f16(acc[0], a, b0[0], b0[1]);
        mma_f16(acc[1], a, b0[2], b0[3]);
        mma_f16(acc[2], a, b1[0], b1[1]);
        mma_f16(acc[3], a, b1[2], b1[3]);
    }

    // ================= K-reduce + store =================
    // half 1 -> smem partials; half 0 adds and stores.
    float* red = (float*)(smem + OFF_RED);   // [8 warps][32 lanes][16 floats]
    if (h == 1) {
        float4* dst = (float4*)(red + (wl * 32 + lid) * 16);
        #pragma unroll
        for (int s = 0; s < 4; ++s)
            dst[s] = make_float4(acc[s][0], acc[s][1], acc[s][2], acc[s][3]);
    }
    __syncthreads();
    if (h == 0) {
        const float4* src = (const float4*)(red + (wl * 32 + lid) * 16);
        const int grp = lid >> 2;
        const int tc  = lid & 3;
        const int row0 = m_base + grp;
        const int row1 = row0 + 8;
        #pragma unroll
        for (int s = 0; s < 4; ++s) {
            float4 p = src[s];
            int col = col0 + n_base + s * 8 + tc * 2;
            *(float2*)(out + (size_t)row0 * NROW + col)
                = make_float2(acc[s][0] + p.x, acc[s][1] + p.y);
            *(float2*)(out + (size_t)row1 * NROW + col)
                = make_float2(acc[s][2] + p.z, acc[s][3] + p.w);
        }
    }
}

extern "C" void kernel_launch(void* const* d_in, const int* in_sizes, int n_in,
                              void* d_out, int out_size) {
    const float* x      = (const float*)d_in[0];
    const float* blocks = (const float*)d_in[1];
    float* out = (float*)d_out;

    cudaFuncSetAttribute(block_diag_hmma,
                         cudaFuncAttributeMaxDynamicSharedMemorySize, SMEM_BYTES);
    block_diag_hmma<<<128, 512, SMEM_BYTES>>>(x, blocks, out);
}

// round 16
// speedup vs baseline: 1.2932x; 1.0188x over previous
#include <cuda_runtime.h>
#include <cuda_fp16.h>
#include <cstdint>

// out[64,8192] = x[64,8192] @ blockdiag(blocks), 32 diagonal 256x256 blocks.
// Grid 128 = 32 blocks x 4 col-chunks of 64. Per CTA:
//   out[0:64, col0:col0+64] = x[0:64, k0:k0+256] @ B[k0:k0+256, col0:col0+64]
//
// Single-term fp16 HMMA (rel_err ~2.9e-4).
// R15: minimize L1 wavefronts. 16 warps = 2 K-halves x (4m x 2n) tiles of
// 16x32 (A x4 fragment reused across two B x4.trans -> 4 MMAs per kstep).
// LDSM wf/CTA: 3072 -> 1536. K-halves combined via 16KB smem reduce.

#define NROW 8192

#define OFF_AH  0          // 32KB: A fp16, 64 rows x 512B, swizzled
#define OFF_BH  32768      // 32KB: B fp16, 256 rows x 128B, swizzled
#define OFF_RED 65536      // 16KB: fp32 partials from K-half 1
#define SMEM_BYTES 81920

__device__ __forceinline__ uint32_t smem_u32(const void* p) {
    uint32_t a;
    asm("{ .reg .u64 t; cvta.to.shared.u64 t, %1; cvt.u32.u64 %0, t; }" : "=r"(a) : "l"(p));
    return a;
}
__device__ __forceinline__ void ldsm_x4(uint32_t* r, uint32_t addr) {
    asm volatile("ldmatrix.sync.aligned.m8n8.x4.shared.b16 {%0,%1,%2,%3}, [%4];"
                 : "=r"(r[0]), "=r"(r[1]), "=r"(r[2]), "=r"(r[3]) : "r"(addr));
}
__device__ __forceinline__ void ldsm_x4_t(uint32_t* r, uint32_t addr) {
    asm volatile("ldmatrix.sync.aligned.m8n8.x4.trans.shared.b16 {%0,%1,%2,%3}, [%4];"
                 : "=r"(r[0]), "=r"(r[1]), "=r"(r[2]), "=r"(r[3]) : "r"(addr));
}
__device__ __forceinline__ void mma_f16(float* d, const uint32_t* a, uint32_t b0, uint32_t b1) {
    asm volatile(
        "mma.sync.aligned.m16n8k16.row.col.f32.f16.f16.f32 "
        "{%0,%1,%2,%3}, {%4,%5,%6,%7}, {%8,%9}, {%0,%1,%2,%3};"
        : "+f"(d[0]), "+f"(d[1]), "+f"(d[2]), "+f"(d[3])
        : "r"(a[0]), "r"(a[1]), "r"(a[2]), "r"(a[3]), "r"(b0), "r"(b1));
}
__device__ __forceinline__ uint32_t h2u(__half2 h) { return *(uint32_t*)&h; }

__global__ void __launch_bounds__(512, 1)
block_diag_hmma(const float* __restrict__ x,
                const float* __restrict__ blocks,
                float* __restrict__ out) {
    extern __shared__ char smem[];
    const uint32_t sbase = smem_u32(smem);

    const int tid   = threadIdx.x;
    const int wid   = tid >> 5;
    const int lid   = tid & 31;
    const int bx    = blockIdx.x;
    const int dblk  = bx >> 2;
    const int chunk = bx & 3;
    const int k0    = dblk * 256;
    const int col0  = k0 + chunk * 64;

    // ================= stage phase =================
    // B first (unique bytes), then A; 8 f4 each per thread, cvt+STS inline.
    {
        char* Bh = smem + OFF_BH;
        #pragma unroll
        for (int p = 0; p < 8; ++p) {
            int idx = p * 512 + tid;
            int k  = idx >> 4;            // 0..255
            int n4 = idx & 15;            // f4 along 64 cols
            float4 v = *(const float4*)(blocks + (size_t)(k0 + k) * NROW + col0 + n4 * 4);
            int g = n4 >> 1;
            uint32_t off = (uint32_t)(k * 128 + ((g ^ (k & 7)) * 16) + (n4 & 1) * 8);
            __half2 b01 = __floats2half2_rn(v.x, v.y);
            __half2 b23 = __floats2half2_rn(v.z, v.w);
            *(uint32_t*)(Bh + off)     = h2u(b01);
            *(uint32_t*)(Bh + off + 4) = h2u(b23);
        }
        char* Ah = smem + OFF_AH;
        #pragma unroll
        for (int p = 0; p < 8; ++p) {
            int idx = p * 512 + tid;
            int m = idx >> 6;             // 0..63
            int q = idx & 63;             // f4 along K
            float4 v = *(const float4*)(x + (size_t)m * NROW + k0 + q * 4);
            int g = q >> 1;
            uint32_t off = (uint32_t)(m * 512 + ((g ^ (m & 7)) * 16) + (q & 1) * 8);
            __half2 a01 = __floats2half2_rn(v.x, v.y);
            __half2 a23 = __floats2half2_rn(v.z, v.w);
            *(uint32_t*)(Ah + off)     = h2u(a01);
            *(uint32_t*)(Ah + off + 4) = h2u(a23);
        }
    }

    __syncthreads();

    // ================= compute phase =================
    // 16 warps = 2 K-halves (h) x 4m x 2n; warp tile 16x32; 8 ksteps per half.
    const int h   = wid >> 3;             // K-half
    const int wl  = wid & 7;
    const int wm  = wl & 3;
    const int wn2 = wl >> 2;              // 0/1 -> n_base 0/32
    const int m_base = wm * 16;
    const int n_base = wn2 * 32;

    const int a_row = m_base + (lid & 15);
    const int a_ch  = lid >> 4;
    const int a_rx  = a_row & 7;
    const uint32_t a_rowbase = sbase + OFF_AH + (uint32_t)(a_row * 512);

    const int l15 = lid & 15;
    const int l7  = lid & 7;
    // two B n-tiles: t0 = wn2*2, t1 = wn2*2+1
    const uint32_t b_lane0 = sbase + OFF_BH
        + (uint32_t)(l15 * 128 + (((wn2 * 4 + 0 + (lid >> 4)) ^ l7) * 16));
    const uint32_t b_lane1 = sbase + OFF_BH
        + (uint32_t)(l15 * 128 + (((wn2 * 4 + 2 + (lid >> 4)) ^ l7) * 16));

    float acc[4][4] = {};                  // 4 n-subtiles of 8 cols
    uint32_t a[4], b0[4], b1[4];

    #pragma unroll
    for (int ks = 0; ks < 8; ++ks) {
        int G = (h * 8 + ks) * 2 + a_ch;   // global 16B granule along K
        uint32_t a_off = a_rowbase + (uint32_t)((G ^ a_rx) * 16);
        uint32_t brow  = (uint32_t)((h * 8 + ks) * 2048);   // 16 k-rows x 128B
        ldsm_x4(a, a_off);
        ldsm_x4_t(b0, b_lane0 + brow);
        ldsm_x4_t(b1, b_lane1 + brow);
        mma_f16(acc[0], a, b0[0], b0[1]);
        mma_f16(acc[1], a, b0[2], b0[3]);
        mma_f16(acc[2], a, b1[0], b1[1]);
        mma_f16(acc[3], a, b1[2], b1[3]);
    }

    // ================= K-reduce + store =================
    // half 1 -> smem partials; half 0 adds and stores.
    float* red = (float*)(smem + OFF_RED);   // [8 warps][32 lanes][16 floats]
    if (h == 1) {
        float4* dst = (float4*)(red + (wl * 32 + lid) * 16);
        #pragma unroll
        for (int s = 0; s < 4; ++s)
            dst[s] = make_float4(acc[s][0], acc[s][1], acc[s][2], acc[s][3]);
    }
    __syncthreads();
    if (h == 0) {
        const float4* src = (const float4*)(red + (wl * 32 + lid) * 16);
        const int grp = lid >> 2;
        const int tc  = lid & 3;
        const int row0 = m_base + grp;
        const int row1 = row0 + 8;
        #pragma unroll
        for (int s = 0; s < 4; ++s) {
            float4 p = src[s];
            int col = col0 + n_base + s * 8 + tc * 2;
            *(float2*)(out + (size_t)row0 * NROW + col)
                = make_float2(acc[s][0] + p.x, acc[s][1] + p.y);
            *(float2*)(out + (size_t)row1 * NROW + col)
                = make_float2(acc[s][2] + p.z, acc[s][3] + p.w);
        }
    }
}

extern "C" void kernel_launch(void* const* d_in, const int* in_sizes, int n_in,
                              void* d_out, int out_size) {
    const float* x      = (const float*)d_in[0];
    const float* blocks = (const float*)d_in[1];
    float* out = (float*)d_out;

    cudaFuncSetAttribute(block_diag_hmma,
                         cudaFuncAttributeMaxDynamicSharedMemorySize, SMEM_BYTES);
    block_diag_hmma<<<128, 512, SMEM_BYTES>>>(x, blocks, out);
}